// round 12
// baseline (speedup 1.0000x reference)
#include <cuda_runtime.h>
#include <cuda_bf16.h>
#include <cstdint>

#define B_    32
#define NHEAD 8
#define NPIX  (B_*64*64)       /* 131072 */
#define NOUT  (B_*32*32)       /* 32768  */

__device__ float d_s0[NHEAD*16];
__device__ float d_qv[NHEAD];
__device__ float d_g[(size_t)NPIX*NHEAD];
__device__ float d_denom[B_*NHEAD];
__device__ float d_v[(size_t)NPIX*256];
__device__ __nv_bfloat16 d_acch[(size_t)NOUT*256], d_accl[(size_t)NOUT*256];
__device__ __nv_bfloat16 d_B1h[65536], d_B1l[65536], d_B2h[65536], d_B2l[65536];

// ---------------------------------------------------------------- helpers
__device__ __forceinline__ uint32_t smem_u32(const void* p) {
    uint32_t a;
    asm("{ .reg .u64 t; cvta.to.shared.u64 t, %1; cvt.u32.u64 %0, t; }" : "=r"(a) : "l"(p));
    return a;
}
__device__ __forceinline__ void ldm_x4(uint32_t* r, uint32_t addr) {
    asm volatile("ldmatrix.sync.aligned.m8n8.x4.shared.b16 {%0,%1,%2,%3}, [%4];"
        : "=r"(r[0]), "=r"(r[1]), "=r"(r[2]), "=r"(r[3]) : "r"(addr));
}
__device__ __forceinline__ void mma_bf16(float* c, const uint32_t* a, const uint32_t* b) {
    asm volatile("mma.sync.aligned.m16n8k16.row.col.f32.bf16.bf16.f32 "
        "{%0,%1,%2,%3}, {%4,%5,%6,%7}, {%8,%9}, {%0,%1,%2,%3};"
        : "+f"(c[0]), "+f"(c[1]), "+f"(c[2]), "+f"(c[3])
        : "r"(a[0]), "r"(a[1]), "r"(a[2]), "r"(a[3]), "r"(b[0]), "r"(b[1]));
}
__device__ __forceinline__ void cpa16(uint32_t dst, const void* src) {
    asm volatile("cp.async.ca.shared.global [%0], [%1], 16;" :: "r"(dst), "l"(src) : "memory");
}
#define CP_COMMIT() asm volatile("cp.async.commit_group;" ::: "memory")
#define CP_WAIT0()  asm volatile("cp.async.wait_group 0;" ::: "memory")
#define CP_WAIT1()  asm volatile("cp.async.wait_group 1;" ::: "memory")

__device__ __forceinline__ uint32_t pack_hi(float a, float b, float& ra, float& rb) {
    __nv_bfloat16 ha = __float2bfloat16(a), hb = __float2bfloat16(b);
    ra = a - __bfloat162float(ha);
    rb = b - __bfloat162float(hb);
    return (uint32_t)__bfloat16_as_ushort(ha) | ((uint32_t)__bfloat16_as_ushort(hb) << 16);
}
__device__ __forceinline__ uint32_t pack_lo(float a, float b) {
    return (uint32_t)__bfloat16_as_ushort(__float2bfloat16(a)) |
           ((uint32_t)__bfloat16_as_ushort(__float2bfloat16(b)) << 16);
}

// ---------------------------------------------------------------------------
// KP: merged prep. Blocks 0..127: weight transpose+split. Block 128: s0/qv/denom.
// ---------------------------------------------------------------------------
__global__ void kp_prep(const float* __restrict__ w1, const float* __restrict__ w2,
                        const float* __restrict__ ne,
                        const float* __restrict__ wkq_w,
                        const float* __restrict__ wkq_b,
                        const float* __restrict__ wgactq_w,
                        const float* __restrict__ wgactq_b) {
    int t = threadIdx.x;
    if (blockIdx.x < 128) {
        int g = blockIdx.x * 256 + t;            // 0..32767
        int mat = g >> 14;
        int r = g & 16383;
        int n = r & 255;
        int k0 = (r >> 8) * 4;
        const float* W = mat ? w2 : w1;
        __nv_bfloat16* Th = mat ? d_B2h : d_B1h;
        __nv_bfloat16* Tl = mat ? d_B2l : d_B1l;
        float x0 = W[(k0+0)*256 + n], x1 = W[(k0+1)*256 + n];
        float x2 = W[(k0+2)*256 + n], x3 = W[(k0+3)*256 + n];
        float r0, r1, r2, r3;
        uint32_t h01 = pack_hi(x0, x1, r0, r1);
        uint32_t h23 = pack_hi(x2, x3, r2, r3);
        *(uint2*)(Th + n*256 + k0) = make_uint2(h01, h23);
        *(uint2*)(Tl + n*256 + k0) = make_uint2(pack_lo(r0, r1), pack_lo(r2, r3));
        return;
    }
    // block 128: tiny prep
    __shared__ float sq[128];
    __shared__ float sk[16][8];
    d_denom[t] = 0.f;
    if (t < 128) {
        float acc = wkq_b[128 + t];
        #pragma unroll 8
        for (int m = 0; m < 128; m++) acc += ne[m] * wkq_w[m*256 + 128 + t];
        sq[t] = acc;
    } else {
        int idx = t - 128, n = idx >> 3, h = idx & 7, col = h * 16;
        const float* nerow = ne + n*128;
        float acc = wkq_b[col];
        #pragma unroll 8
        for (int m = 0; m < 128; m++) acc += nerow[m] * wkq_w[m*256 + col];
        sk[n][h] = acc;
    }
    __syncthreads();
    if (t < 8) {
        float l[16], mx = -1e30f;
        #pragma unroll
        for (int j = 0; j < 16; j++) { l[j] = sq[t*16 + j] + sk[j][t]; mx = fmaxf(mx, l[j]); }
        float s = 0.f;
        #pragma unroll
        for (int j = 0; j < 16; j++) { l[j] = expf(l[j] - mx); s += l[j]; }
        #pragma unroll
        for (int j = 0; j < 16; j++) d_s0[t*16 + j] = l[j] / s;
    } else if (t < 16) {
        int nh = t - 8;
        const float* nerow = ne + 14*128;
        float acc = wgactq_b[nh];
        #pragma unroll 8
        for (int m = 0; m < 128; m++) acc += nerow[m] * wgactq_w[m*8 + nh];
        d_qv[nh] = acc;
    }
}

// ---------------------------------------------------------------------------
// K1: g = relu(qv + inps @ wgactk + b) + per-(b,h) denom  (lean)
// ---------------------------------------------------------------------------
__global__ void k1_act(const float* __restrict__ inps,
                       const float* __restrict__ wk,
                       const float* __restrict__ wkb) {
    __shared__ float sw[8 * 256];
    __shared__ float sden[NHEAD];
    int t = threadIdx.x;
    for (int i = t; i < 2048; i += 256) {
        int c = i >> 3, nh = i & 7;
        sw[nh*256 + c] = wk[i];
    }
    if (t < 8) sden[t] = 0.f;
    __syncthreads();
    int b = blockIdx.y;
    int lane = t & 31, warp = t >> 5;
    int pix0 = b * 4096 + blockIdx.x * 256;
    for (int it = warp; it < 256; it += 8) {
        int p = pix0 + it;
        const float* row = inps + (size_t)p * 256;
        float acc[8];
        #pragma unroll
        for (int n = 0; n < 8; n++) acc[n] = 0.f;
        #pragma unroll
        for (int q = 0; q < 8; q++) {
            float xv = row[lane + 32*q];
            #pragma unroll
            for (int n = 0; n < 8; n++) acc[n] += xv * sw[n*256 + lane + 32*q];
        }
        #pragma unroll
        for (int off = 16; off; off >>= 1)
            #pragma unroll
            for (int n = 0; n < 8; n++) acc[n] += __shfl_xor_sync(0xffffffffu, acc[n], off);
        if (lane < 8) {
            float gv = fmaxf(0.f, d_qv[lane] + acc[lane] + wkb[lane]);
            d_g[(size_t)p*8 + lane] = gv;
            atomicAdd(&sden[lane], gv);
        }
    }
    __syncthreads();
    if (t < 8) atomicAdd(&d_denom[b*8 + t], sden[t]);
}

// ---------------------------------------------------------------------------
// mma.sync bf16 split-3 GEMM. Block 128x256, 8 warps (64x64 tile each),
// K-step 32, double-buffered smem, B via cp.async.
// MODE 0: A = fp32 inps staged via cp.async, converted smem->smem in-loop.
// MODE 1: A = pre-split bf16 (d_acch/d_accl) via cp.async.
// ---------------------------------------------------------------------------
#define SA_H 0
#define SA_L 10240
#define SB_H 20480
#define SB_L 40960
#define BUFSTR 61440
#define SSTG  (2*BUFSTR)             /* fp32 staging: 2 x 16384 */
#define SBIAS (SSTG + 32768)
#define SMT   (SBIAS + 1024)

template<int MODE>
__global__ void __launch_bounds__(256) gemm_mma(const float* __restrict__ Afp,
                                                const float* __restrict__ bias,
                                                float* __restrict__ outp) {
    extern __shared__ char smc[];
    const __nv_bfloat16* Bhg = (MODE == 0) ? d_B1h : d_B2h;
    const __nv_bfloat16* Blg = (MODE == 0) ? d_B1l : d_B2l;
    float* Cp = (MODE == 0) ? d_v : outp;

    int t = threadIdx.x, lane = t & 31, wid = t >> 5;
    int wm = wid & 1, wn = wid >> 1;         // 2 x 4 warp grid, 64x64 tiles
    int bm = blockIdx.x * 128;
    uint32_t sb = smem_u32(smc);

    float* sbias = (float*)(smc + SBIAS);
    sbias[t] = bias[t];                      // 256 threads cover 256 cols

    auto issue = [&](int kc, int buf) {
        uint32_t base = sb + buf * BUFSTR;
        if (MODE == 0) {
            uint32_t stg = sb + SSTG + buf * 16384;
            #pragma unroll
            for (int j = 0; j < 4; j++) {
                int idx = t + 256*j;                    // 0..1023
                int row = idx >> 3, seg = idx & 7;
                cpa16(stg + (uint32_t)idx * 16,
                      Afp + (size_t)(bm + row) * 256 + kc * 32 + seg * 4);
            }
        } else {
            #pragma unroll
            for (int j = 0; j < 2; j++) {
                int idx = t + 256*j;                    // 0..511
                int arow = idx >> 2, aseg = idx & 3;
                uint32_t dstA = (uint32_t)(arow * 80 + aseg * 16);
                cpa16(base + SA_H + dstA, d_acch + (size_t)(bm + arow) * 256 + kc * 32 + aseg * 8);
                cpa16(base + SA_L + dstA, d_accl + (size_t)(bm + arow) * 256 + kc * 32 + aseg * 8);
            }
        }
        #pragma unroll
        for (int j = 0; j < 4; j++) {
            int idx = t + 256 * j;                      // 0..1023
            int brow = idx >> 2, bseg = idx & 3;
            uint32_t dstB = (uint32_t)(brow * 80 + bseg * 16);
            cpa16(base + SB_H + dstB, Bhg + (size_t)brow * 256 + kc * 32 + bseg * 8);
            cpa16(base + SB_L + dstB, Blg + (size_t)brow * 256 + kc * 32 + bseg * 8);
        }
        CP_COMMIT();
    };

    auto convertA = [&](int kc) {
        if (MODE != 0) return;
        int buf = kc & 1;
        const char* stg = smc + SSTG + buf * 16384;
        #pragma unroll
        for (int j = 0; j < 4; j++) {
            int idx = t + 256*j;                        // 0..1023
            int row = idx >> 3, c4 = idx & 7;
            float4 x = *(const float4*)(stg + (size_t)idx * 16);
            float ra, rb, rc, rd;
            uint32_t h01 = pack_hi(x.x, x.y, ra, rb);
            uint32_t h23 = pack_hi(x.z, x.w, rc, rd);
            uint32_t off = (uint32_t)(buf * BUFSTR + row * 80 + c4 * 8);
            *(uint2*)(smc + SA_H + off) = make_uint2(h01, h23);
            *(uint2*)(smc + SA_L + off) = make_uint2(pack_lo(ra, rb), pack_lo(rc, rd));
        }
    };

    int mat = lane >> 3, r8 = lane & 7;
    uint32_t aBase = (uint32_t)((wm*64 + (mat & 1)*8 + r8) * 80 + ((mat >> 1)*8) * 2);
    uint32_t bBase = (uint32_t)((wn*64 + (mat >> 1)*8 + r8) * 80 + ((mat & 1)*8) * 2);

    float acc[4][8][4];
    #pragma unroll
    for (int i = 0; i < 4; i++)
        #pragma unroll
        for (int j = 0; j < 8; j++)
            #pragma unroll
            for (int q = 0; q < 4; q++) acc[i][j][q] = 0.f;

    issue(0, 0);
    issue(1, 1);
    CP_WAIT1();                 // group 0 arrived
    __syncthreads();
    convertA(0);
    __syncthreads();

    #pragma unroll
    for (int ks = 0; ks < 8; ks++) {
        int buf = ks & 1;
        uint32_t abuf = sb + buf * BUFSTR;

        #pragma unroll
        for (int kk = 0; kk < 2; kk++) {
            uint32_t kb = kk * 32;
            uint32_t ah[4][4], al[4][4];
            #pragma unroll
            for (int mt = 0; mt < 4; mt++) {
                ldm_x4(ah[mt], abuf + SA_H + aBase + mt*16*80 + kb);
                ldm_x4(al[mt], abuf + SA_L + aBase + mt*16*80 + kb);
            }
            #pragma unroll
            for (int h = 0; h < 2; h++) {
                uint32_t bh[4][2], bl[4][2];
                #pragma unroll
                for (int pp = 0; pp < 2; pp++) {
                    int p = 2*h + pp;
                    uint32_t tmp[4];
                    ldm_x4(tmp, abuf + SB_H + bBase + p*16*80 + kb);
                    bh[2*pp][0] = tmp[0]; bh[2*pp][1] = tmp[1];
                    bh[2*pp+1][0] = tmp[2]; bh[2*pp+1][1] = tmp[3];
                    ldm_x4(tmp, abuf + SB_L + bBase + p*16*80 + kb);
                    bl[2*pp][0] = tmp[0]; bl[2*pp][1] = tmp[1];
                    bl[2*pp+1][0] = tmp[2]; bl[2*pp+1][1] = tmp[3];
                }
                #pragma unroll
                for (int mt = 0; mt < 4; mt++)
                    #pragma unroll
                    for (int nn = 0; nn < 4; nn++) {
                        int nt = 4*h + nn;
                        mma_bf16(acc[mt][nt], ah[mt], bh[nn]);
                        mma_bf16(acc[mt][nt], ah[mt], bl[nn]);
                        mma_bf16(acc[mt][nt], al[mt], bh[nn]);
                    }
            }
        }
        __syncthreads();                       // MMA reads done before refill

        if (ks < 6) issue(ks + 2, buf);        // refill buffer just freed
        if (ks < 7) {
            if (ks < 6) { CP_WAIT1(); } else { CP_WAIT0(); }   // group ks+1 arrived
            __syncthreads();
            convertA(ks + 1);
            __syncthreads();
        }
    }

    // epilogue
    int bb = bm >> 12;
    float invd0 = 0.f, invd1 = 0.f;
    if (MODE == 0) {
        invd0 = 4096.f / (d_denom[bb*8 + wn*2 + 0] + 1e-6f);
        invd1 = 4096.f / (d_denom[bb*8 + wn*2 + 1] + 1e-6f);
    }
    #pragma unroll
    for (int mt = 0; mt < 4; mt++) {
        #pragma unroll
        for (int hf = 0; hf < 2; hf++) {
            int row = bm + wm*64 + mt*16 + hf*8 + (lane >> 2);
            float* dst = Cp + (size_t)row * 256;
            float g0 = 0.f, g1 = 0.f;
            if (MODE == 0) {
                g0 = d_g[(size_t)row*8 + wn*2 + 0] * invd0;
                g1 = d_g[(size_t)row*8 + wn*2 + 1] * invd1;
            }
            #pragma unroll
            for (int nt = 0; nt < 8; nt++) {
                int col = wn*64 + nt*8 + (lane & 3)*2;
                float v0 = acc[mt][nt][hf*2+0] + sbias[col];
                float v1 = acc[mt][nt][hf*2+1] + sbias[col + 1];
                if (MODE == 0) {
                    float s = (nt < 4) ? g0 : g1;
                    v0 *= s; v1 *= s;
                }
                *(float2*)(dst + col) = make_float2(v0, v1);
            }
        }
    }
}

// ---------------------------------------------------------------------------
// K4a: patch gather, float4-vectorized, 2x2 output tile per block.
// ---------------------------------------------------------------------------
__global__ void __launch_bounds__(256) k4a_gather() {
    __shared__ float ss0[128];
    int t = threadIdx.x;
    if (t < 128) ss0[t] = d_s0[t];
    __syncthreads();

    int op = blockIdx.x;                    // 0..8191
    int b  = op >> 8;
    int xt = (op >> 4) & 15, yt = op & 15;
    int out = t >> 6;
    int x = 2*xt + (out >> 1);
    int y = 2*yt + (out & 1);
    int cq = t & 63;                        // float4 index
    int h = cq >> 3;

    float s[16];
    #pragma unroll
    for (int n = 0; n < 16; n++) s[n] = ss0[h*16 + n];

    const float4* V4 = (const float4*)d_v;
    float4 a4 = make_float4(0.f, 0.f, 0.f, 0.f);
    #pragma unroll
    for (int i = 0; i < 4; i++) {
        int sh = 2*x + i - 1;
        if ((unsigned)sh >= 64u) continue;
        #pragma unroll
        for (int j = 0; j < 4; j++) {
            int sw = 2*y + j - 1;
            if ((unsigned)sw >= 64u) continue;
            float4 vv = V4[(((size_t)b*64 + sh)*64 + sw)*64 + cq];
            float w = s[i*4 + j];
            a4.x += w * vv.x; a4.y += w * vv.y;
            a4.z += w * vv.z; a4.w += w * vv.w;
        }
    }

    size_t idx = ((size_t)((b*32 + x)*32 + y))*256 + cq*4;
    float ra, rb, rc, rd;
    uint32_t h01 = pack_hi(a4.x, a4.y, ra, rb);
    uint32_t h23 = pack_hi(a4.z, a4.w, rc, rd);
    *(uint2*)(d_acch + idx) = make_uint2(h01, h23);
    *(uint2*)(d_accl + idx) = make_uint2(pack_lo(ra, rb), pack_lo(rc, rd));
}

// ---------------------------------------------------------------------------
extern "C" void kernel_launch(void* const* d_in, const int* in_sizes, int n_in,
                              void* d_out, int out_size) {
    const float* inps     = (const float*)d_in[0];
    const float* ne       = (const float*)d_in[1];
    const float* wkq_w    = (const float*)d_in[2];
    const float* wkq_b    = (const float*)d_in[3];
    const float* wv_w     = (const float*)d_in[4];
    const float* wv_b     = (const float*)d_in[5];
    const float* wgactq_w = (const float*)d_in[6];
    const float* wgactq_b = (const float*)d_in[7];
    const float* wgactk_w = (const float*)d_in[8];
    const float* wgactk_b = (const float*)d_in[9];
    const float* wf_w     = (const float*)d_in[10];
    const float* wf_b     = (const float*)d_in[11];
    float* out = (float*)d_out;

    static int inited = 0;
    if (!inited) {
        cudaFuncSetAttribute(gemm_mma<0>, cudaFuncAttributeMaxDynamicSharedMemorySize, SMT);
        cudaFuncSetAttribute(gemm_mma<1>, cudaFuncAttributeMaxDynamicSharedMemorySize, SMT);
        inited = 1;
    }

    kp_prep<<<129, 256>>>(wv_w, wf_w, ne, wkq_w, wkq_b, wgactq_w, wgactq_b);
    k1_act<<<dim3(16, 32), 256>>>(inps, wgactk_w, wgactk_b);
    gemm_mma<0><<<1024, 256, SMT>>>(inps, wv_b, nullptr);
    k4a_gather<<<8192, 256>>>();
    gemm_mma<1><<<256, 256, SMT>>>(nullptr, wf_b, out);
}

// round 13
// speedup vs baseline: 1.2683x; 1.2683x over previous
#include <cuda_runtime.h>
#include <cuda_fp16.h>
#include <cstdint>

#define B_    32
#define NHEAD 8
#define NPIX  (B_*64*64)       /* 131072 */
#define NOUT  (B_*32*32)       /* 32768  */

__device__ float d_s0[NHEAD*16];
__device__ float d_qv[NHEAD];
__device__ float d_g[(size_t)NPIX*NHEAD];
__device__ float d_denom[B_*NHEAD];
__device__ float d_v[(size_t)NPIX*256];
__device__ __half d_acch[(size_t)NOUT*256], d_accl[(size_t)NOUT*256];
__device__ __half d_B1[65536], d_B2[65536];    /* W^T [n][k], single fp16 */

// ---------------------------------------------------------------- helpers
__device__ __forceinline__ uint32_t smem_u32(const void* p) {
    uint32_t a;
    asm("{ .reg .u64 t; cvta.to.shared.u64 t, %1; cvt.u32.u64 %0, t; }" : "=r"(a) : "l"(p));
    return a;
}
__device__ __forceinline__ void ldm_x4(uint32_t* r, uint32_t addr) {
    asm volatile("ldmatrix.sync.aligned.m8n8.x4.shared.b16 {%0,%1,%2,%3}, [%4];"
        : "=r"(r[0]), "=r"(r[1]), "=r"(r[2]), "=r"(r[3]) : "r"(addr));
}
__device__ __forceinline__ void mma_f16(float* c, const uint32_t* a, const uint32_t* b) {
    asm volatile("mma.sync.aligned.m16n8k16.row.col.f32.f16.f16.f32 "
        "{%0,%1,%2,%3}, {%4,%5,%6,%7}, {%8,%9}, {%0,%1,%2,%3};"
        : "+f"(c[0]), "+f"(c[1]), "+f"(c[2]), "+f"(c[3])
        : "r"(a[0]), "r"(a[1]), "r"(a[2]), "r"(a[3]), "r"(b[0]), "r"(b[1]));
}
__device__ __forceinline__ void cpa16(uint32_t dst, const void* src) {
    asm volatile("cp.async.ca.shared.global [%0], [%1], 16;" :: "r"(dst), "l"(src) : "memory");
}
#define CP_COMMIT() asm volatile("cp.async.commit_group;" ::: "memory")
#define CP_WAIT0()  asm volatile("cp.async.wait_group 0;" ::: "memory")
#define CP_WAIT1()  asm volatile("cp.async.wait_group 1;" ::: "memory")

__device__ __forceinline__ uint32_t pack16(float a, float b) {
    return (uint32_t)__half_as_ushort(__float2half_rn(a)) |
           ((uint32_t)__half_as_ushort(__float2half_rn(b)) << 16);
}
__device__ __forceinline__ uint32_t pack_hi16(float a, float b, float& ra, float& rb) {
    __half ha = __float2half_rn(a), hb = __float2half_rn(b);
    ra = a - __half2float(ha);
    rb = b - __half2float(hb);
    return (uint32_t)__half_as_ushort(ha) | ((uint32_t)__half_as_ushort(hb) << 16);
}

// ---------------------------------------------------------------------------
// KP: merged prep. Blocks 0..127: weight transpose to fp16. Block 128: s0/qv/denom.
// ---------------------------------------------------------------------------
__global__ void kp_prep(const float* __restrict__ w1, const float* __restrict__ w2,
                        const float* __restrict__ ne,
                        const float* __restrict__ wkq_w,
                        const float* __restrict__ wkq_b,
                        const float* __restrict__ wgactq_w,
                        const float* __restrict__ wgactq_b) {
    int t = threadIdx.x;
    if (blockIdx.x < 128) {
        int g = blockIdx.x * 256 + t;            // 0..32767
        int mat = g >> 14;
        int r = g & 16383;
        int n = r & 255;
        int k0 = (r >> 8) * 4;
        const float* W = mat ? w2 : w1;
        __half* T = mat ? d_B2 : d_B1;
        float x0 = W[(k0+0)*256 + n], x1 = W[(k0+1)*256 + n];
        float x2 = W[(k0+2)*256 + n], x3 = W[(k0+3)*256 + n];
        *(uint2*)(T + n*256 + k0) = make_uint2(pack16(x0, x1), pack16(x2, x3));
        return;
    }
    // block 128: tiny prep
    __shared__ float sq[128];
    __shared__ float sk[16][8];
    d_denom[t] = 0.f;
    if (t < 128) {
        float acc = wkq_b[128 + t];
        #pragma unroll 8
        for (int m = 0; m < 128; m++) acc += ne[m] * wkq_w[m*256 + 128 + t];
        sq[t] = acc;
    } else {
        int idx = t - 128, n = idx >> 3, h = idx & 7, col = h * 16;
        const float* nerow = ne + n*128;
        float acc = wkq_b[col];
        #pragma unroll 8
        for (int m = 0; m < 128; m++) acc += nerow[m] * wkq_w[m*256 + col];
        sk[n][h] = acc;
    }
    __syncthreads();
    if (t < 8) {
        float l[16], mx = -1e30f;
        #pragma unroll
        for (int j = 0; j < 16; j++) { l[j] = sq[t*16 + j] + sk[j][t]; mx = fmaxf(mx, l[j]); }
        float s = 0.f;
        #pragma unroll
        for (int j = 0; j < 16; j++) { l[j] = expf(l[j] - mx); s += l[j]; }
        #pragma unroll
        for (int j = 0; j < 16; j++) d_s0[t*16 + j] = l[j] / s;
    } else if (t < 16) {
        int nh = t - 8;
        const float* nerow = ne + 14*128;
        float acc = wgactq_b[nh];
        #pragma unroll 8
        for (int m = 0; m < 128; m++) acc += nerow[m] * wgactq_w[m*8 + nh];
        d_qv[nh] = acc;
    }
}

// ---------------------------------------------------------------------------
// K1: g = relu(qv + inps @ wgactk + b) + per-(b,h) denom  (lean)
// ---------------------------------------------------------------------------
__global__ void k1_act(const float* __restrict__ inps,
                       const float* __restrict__ wk,
                       const float* __restrict__ wkb) {
    __shared__ float sw[8 * 256];
    __shared__ float sden[NHEAD];
    int t = threadIdx.x;
    for (int i = t; i < 2048; i += 256) {
        int c = i >> 3, nh = i & 7;
        sw[nh*256 + c] = wk[i];
    }
    if (t < 8) sden[t] = 0.f;
    __syncthreads();
    int b = blockIdx.y;
    int lane = t & 31, warp = t >> 5;
    int pix0 = b * 4096 + blockIdx.x * 256;
    for (int it = warp; it < 256; it += 8) {
        int p = pix0 + it;
        const float* row = inps + (size_t)p * 256;
        float acc[8];
        #pragma unroll
        for (int n = 0; n < 8; n++) acc[n] = 0.f;
        #pragma unroll
        for (int q = 0; q < 8; q++) {
            float xv = row[lane + 32*q];
            #pragma unroll
            for (int n = 0; n < 8; n++) acc[n] += xv * sw[n*256 + lane + 32*q];
        }
        #pragma unroll
        for (int off = 16; off; off >>= 1)
            #pragma unroll
            for (int n = 0; n < 8; n++) acc[n] += __shfl_xor_sync(0xffffffffu, acc[n], off);
        if (lane < 8) {
            float gv = fmaxf(0.f, d_qv[lane] + acc[lane] + wkb[lane]);
            d_g[(size_t)p*8 + lane] = gv;
            atomicAdd(&sden[lane], gv);
        }
    }
    __syncthreads();
    if (t < 8) atomicAdd(&d_denom[b*8 + t], sden[t]);
}

// ---------------------------------------------------------------------------
// mma.sync fp16 split-2 GEMM. Block 128x256, 16 warps (32x64), K-step 32,
// double-buffered smem. A split fp16 hi/lo (exact), B single fp16.
// MODE 0: A = fp32 inps staged via cp.async, converted smem->smem in-loop.
// MODE 1: A = pre-split fp16 (d_acch/d_accl) via cp.async.
// ---------------------------------------------------------------------------
#define SA_H 0
#define SA_L 10240
#define SB_  20480
#define BUFSTR 40960
#define SSTG  (2*BUFSTR)             /* fp32 staging: 2 x 16384 */
#define SBIAS (SSTG + 32768)
#define SMT   (SBIAS + 1024)

template<int MODE>
__global__ void __launch_bounds__(512) gemm_mma(const float* __restrict__ Afp,
                                                const float* __restrict__ bias,
                                                float* __restrict__ outp) {
    extern __shared__ char smc[];
    const __half* Bg = (MODE == 0) ? d_B1 : d_B2;
    float* Cp = (MODE == 0) ? d_v : outp;

    int t = threadIdx.x, lane = t & 31, wid = t >> 5;
    int wm = wid & 3, wn = wid >> 2;         // 4 x 4 warp grid, 32x64 tiles
    int bm = blockIdx.x * 128;
    uint32_t sb = smem_u32(smc);

    float* sbias = (float*)(smc + SBIAS);
    if (t < 256) sbias[t] = bias[t];

    auto issue = [&](int kc, int buf) {
        uint32_t base = sb + buf * BUFSTR;
        if (MODE == 0) {
            uint32_t stg = sb + SSTG + buf * 16384;
            #pragma unroll
            for (int j = 0; j < 2; j++) {
                int idx = t + 512*j;
                int row = idx >> 3, seg = idx & 7;
                cpa16(stg + (uint32_t)idx * 16,
                      Afp + (size_t)(bm + row) * 256 + kc * 32 + seg * 4);
            }
        } else {
            int arow = t >> 2, aseg = t & 3;
            uint32_t dstA = (uint32_t)(arow * 80 + aseg * 16);
            cpa16(base + SA_H + dstA, d_acch + (size_t)(bm + arow) * 256 + kc * 32 + aseg * 8);
            cpa16(base + SA_L + dstA, d_accl + (size_t)(bm + arow) * 256 + kc * 32 + aseg * 8);
        }
        #pragma unroll
        for (int j = 0; j < 2; j++) {
            int idx = t + 512 * j;
            int brow = idx >> 2, bseg = idx & 3;
            uint32_t dstB = (uint32_t)(brow * 80 + bseg * 16);
            cpa16(base + SB_ + dstB, Bg + (size_t)brow * 256 + kc * 32 + bseg * 8);
        }
        CP_COMMIT();
    };

    auto convertA = [&](int kc) {
        if (MODE != 0) return;
        int buf = kc & 1;
        const char* stg = smc + SSTG + buf * 16384;
        #pragma unroll
        for (int j = 0; j < 2; j++) {
            int idx = t + 512*j;
            int row = idx >> 3, c4 = idx & 7;
            float4 x = *(const float4*)(stg + (size_t)idx * 16);
            float ra, rb, rc, rd;
            uint32_t h01 = pack_hi16(x.x, x.y, ra, rb);
            uint32_t h23 = pack_hi16(x.z, x.w, rc, rd);
            uint32_t off = (uint32_t)(buf * BUFSTR + row * 80 + c4 * 8);
            *(uint2*)(smc + SA_H + off) = make_uint2(h01, h23);
            *(uint2*)(smc + SA_L + off) = make_uint2(pack16(ra, rb), pack16(rc, rd));
        }
    };

    int mat = lane >> 3, r8 = lane & 7;
    uint32_t aBase = (uint32_t)((wm*32 + (mat & 1)*8 + r8) * 80 + ((mat >> 1)*8) * 2);
    uint32_t bBase = (uint32_t)((wn*64 + (mat >> 1)*8 + r8) * 80 + ((mat & 1)*8) * 2);

    float acc[2][8][4];
    #pragma unroll
    for (int i = 0; i < 2; i++)
        #pragma unroll
        for (int j = 0; j < 8; j++)
            #pragma unroll
            for (int q = 0; q < 4; q++) acc[i][j][q] = 0.f;

    issue(0, 0);
    issue(1, 1);
    CP_WAIT1();                 // group 0 arrived
    __syncthreads();
    convertA(0);
    __syncthreads();

    #pragma unroll
    for (int ks = 0; ks < 8; ks++) {
        int buf = ks & 1;
        uint32_t abuf = sb + buf * BUFSTR;

        #pragma unroll
        for (int kk = 0; kk < 2; kk++) {
            uint32_t kb = kk * 32;
            uint32_t ah[2][4], al[2][4];
            #pragma unroll
            for (int mt = 0; mt < 2; mt++) {
                ldm_x4(ah[mt], abuf + SA_H + aBase + mt*16*80 + kb);
                ldm_x4(al[mt], abuf + SA_L + aBase + mt*16*80 + kb);
            }
            #pragma unroll
            for (int h = 0; h < 2; h++) {
                uint32_t bh[4][2];
                #pragma unroll
                for (int pp = 0; pp < 2; pp++) {
                    int p = 2*h + pp;
                    uint32_t tmp[4];
                    ldm_x4(tmp, abuf + SB_ + bBase + p*16*80 + kb);
                    bh[2*pp][0] = tmp[0]; bh[2*pp][1] = tmp[1];
                    bh[2*pp+1][0] = tmp[2]; bh[2*pp+1][1] = tmp[3];
                }
                #pragma unroll
                for (int mt = 0; mt < 2; mt++)
                    #pragma unroll
                    for (int nn = 0; nn < 4; nn++) {
                        int nt = 4*h + nn;
                        mma_f16(acc[mt][nt], ah[mt], bh[nn]);
                        mma_f16(acc[mt][nt], al[mt], bh[nn]);
                    }
            }
        }
        __syncthreads();                       // MMA reads done before refill

        if (ks < 6) issue(ks + 2, buf);        // refill buffer just freed
        if (ks < 7) {
            if (ks < 6) { CP_WAIT1(); } else { CP_WAIT0(); }   // group ks+1 arrived
            __syncthreads();
            convertA(ks + 1);
            __syncthreads();
        }
    }

    // epilogue
    int bb = bm >> 12;
    float invd0 = 0.f, invd1 = 0.f;
    if (MODE == 0) {
        invd0 = 4096.f / (d_denom[bb*8 + wn*2 + 0] + 1e-6f);
        invd1 = 4096.f / (d_denom[bb*8 + wn*2 + 1] + 1e-6f);
    }
    #pragma unroll
    for (int mt = 0; mt < 2; mt++) {
        #pragma unroll
        for (int hf = 0; hf < 2; hf++) {
            int row = bm + wm*32 + mt*16 + hf*8 + (lane >> 2);
            float* dst = Cp + (size_t)row * 256;
            float g0 = 0.f, g1 = 0.f;
            if (MODE == 0) {
                g0 = d_g[(size_t)row*8 + wn*2 + 0] * invd0;
                g1 = d_g[(size_t)row*8 + wn*2 + 1] * invd1;
            }
            #pragma unroll
            for (int nt = 0; nt < 8; nt++) {
                int col = wn*64 + nt*8 + (lane & 3)*2;
                float v0 = acc[mt][nt][hf*2+0] + sbias[col];
                float v1 = acc[mt][nt][hf*2+1] + sbias[col + 1];
                if (MODE == 0) {
                    float s = (nt < 4) ? g0 : g1;
                    v0 *= s; v1 *= s;
                }
                *(float2*)(dst + col) = make_float2(v0, v1);
            }
        }
    }
}

// ---------------------------------------------------------------------------
// K4a: patch gather, float4-vectorized, 2x2 output tile per block,
// outputs fp16 hi/lo for GEMM2.
// ---------------------------------------------------------------------------
__global__ void __launch_bounds__(256) k4a_gather() {
    __shared__ float ss0[128];
    int t = threadIdx.x;
    if (t < 128) ss0[t] = d_s0[t];
    __syncthreads();

    int op = blockIdx.x;                    // 0..8191
    int b  = op >> 8;
    int xt = (op >> 4) & 15, yt = op & 15;
    int out = t >> 6;
    int x = 2*xt + (out >> 1);
    int y = 2*yt + (out & 1);
    int cq = t & 63;                        // float4 index
    int h = cq >> 3;

    float s[16];
    #pragma unroll
    for (int n = 0; n < 16; n++) s[n] = ss0[h*16 + n];

    const float4* V4 = (const float4*)d_v;
    float4 a4 = make_float4(0.f, 0.f, 0.f, 0.f);
    #pragma unroll
    for (int i = 0; i < 4; i++) {
        int sh = 2*x + i - 1;
        if ((unsigned)sh >= 64u) continue;
        #pragma unroll
        for (int j = 0; j < 4; j++) {
            int sw = 2*y + j - 1;
            if ((unsigned)sw >= 64u) continue;
            float4 vv = V4[(((size_t)b*64 + sh)*64 + sw)*64 + cq];
            float w = s[i*4 + j];
            a4.x += w * vv.x; a4.y += w * vv.y;
            a4.z += w * vv.z; a4.w += w * vv.w;
        }
    }

    size_t idx = ((size_t)((b*32 + x)*32 + y))*256 + cq*4;
    float ra, rb, rc, rd;
    uint32_t h01 = pack_hi16(a4.x, a4.y, ra, rb);
    uint32_t h23 = pack_hi16(a4.z, a4.w, rc, rd);
    *(uint2*)(d_acch + idx) = make_uint2(h01, h23);
    *(uint2*)(d_accl + idx) = make_uint2(pack16(ra, rb), pack16(rc, rd));
}

// ---------------------------------------------------------------------------
extern "C" void kernel_launch(void* const* d_in, const int* in_sizes, int n_in,
                              void* d_out, int out_size) {
    const float* inps     = (const float*)d_in[0];
    const float* ne       = (const float*)d_in[1];
    const float* wkq_w    = (const float*)d_in[2];
    const float* wkq_b    = (const float*)d_in[3];
    const float* wv_w     = (const float*)d_in[4];
    const float* wv_b     = (const float*)d_in[5];
    const float* wgactq_w = (const float*)d_in[6];
    const float* wgactq_b = (const float*)d_in[7];
    const float* wgactk_w = (const float*)d_in[8];
    const float* wgactk_b = (const float*)d_in[9];
    const float* wf_w     = (const float*)d_in[10];
    const float* wf_b     = (const float*)d_in[11];
    float* out = (float*)d_out;

    static int inited = 0;
    if (!inited) {
        cudaFuncSetAttribute(gemm_mma<0>, cudaFuncAttributeMaxDynamicSharedMemorySize, SMT);
        cudaFuncSetAttribute(gemm_mma<1>, cudaFuncAttributeMaxDynamicSharedMemorySize, SMT);
        inited = 1;
    }

    kp_prep<<<129, 256>>>(wv_w, wf_w, ne, wkq_w, wkq_b, wgactq_w, wgactq_b);
    k1_act<<<dim3(16, 32), 256>>>(inps, wgactk_w, wgactk_b);
    gemm_mma<0><<<1024, 512, SMT>>>(inps, wv_b, nullptr);
    k4a_gather<<<8192, 256>>>();
    gemm_mma<1><<<256, 512, SMT>>>(nullptr, wf_b, out);
}

// round 14
// speedup vs baseline: 1.3516x; 1.0656x over previous
#include <cuda_runtime.h>
#include <cuda_fp16.h>
#include <cstdint>

#define B_    32
#define NHEAD 8
#define NPIX  (B_*64*64)       /* 131072 */
#define NOUT  (B_*32*32)       /* 32768  */

__device__ float d_s0[NHEAD*16];
__device__ float d_qv[NHEAD];
__device__ float d_g[(size_t)NPIX*NHEAD];
__device__ float d_denom[B_*NHEAD];
__device__ __half d_v[(size_t)NPIX*256];          /* v in fp16 */
__device__ __half d_acc[(size_t)NOUT*256];        /* gathered acc, single fp16 */
__device__ __half d_B1[65536], d_B2[65536];       /* W^T [n][k], fp16 */

// ---------------------------------------------------------------- helpers
__device__ __forceinline__ uint32_t smem_u32(const void* p) {
    uint32_t a;
    asm("{ .reg .u64 t; cvta.to.shared.u64 t, %1; cvt.u32.u64 %0, t; }" : "=r"(a) : "l"(p));
    return a;
}
__device__ __forceinline__ void ldm_x4(uint32_t* r, uint32_t addr) {
    asm volatile("ldmatrix.sync.aligned.m8n8.x4.shared.b16 {%0,%1,%2,%3}, [%4];"
        : "=r"(r[0]), "=r"(r[1]), "=r"(r[2]), "=r"(r[3]) : "r"(addr));
}
__device__ __forceinline__ void mma_f16(float* c, const uint32_t* a, const uint32_t* b) {
    asm volatile("mma.sync.aligned.m16n8k16.row.col.f32.f16.f16.f32 "
        "{%0,%1,%2,%3}, {%4,%5,%6,%7}, {%8,%9}, {%0,%1,%2,%3};"
        : "+f"(c[0]), "+f"(c[1]), "+f"(c[2]), "+f"(c[3])
        : "r"(a[0]), "r"(a[1]), "r"(a[2]), "r"(a[3]), "r"(b[0]), "r"(b[1]));
}
__device__ __forceinline__ void cpa16(uint32_t dst, const void* src) {
    asm volatile("cp.async.ca.shared.global [%0], [%1], 16;" :: "r"(dst), "l"(src) : "memory");
}
#define CP_COMMIT() asm volatile("cp.async.commit_group;" ::: "memory")
#define CP_WAIT0()  asm volatile("cp.async.wait_group 0;" ::: "memory")
#define CP_WAIT1()  asm volatile("cp.async.wait_group 1;" ::: "memory")

__device__ __forceinline__ uint32_t pack16(float a, float b) {
    return (uint32_t)__half_as_ushort(__float2half_rn(a)) |
           ((uint32_t)__half_as_ushort(__float2half_rn(b)) << 16);
}
__device__ __forceinline__ uint32_t pack_hi16(float a, float b, float& ra, float& rb) {
    __half ha = __float2half_rn(a), hb = __float2half_rn(b);
    ra = a - __half2float(ha);
    rb = b - __half2float(hb);
    return (uint32_t)__half_as_ushort(ha) | ((uint32_t)__half_as_ushort(hb) << 16);
}

// ---------------------------------------------------------------------------
// KP: merged prep. Blocks 0..127: weight transpose to fp16. Block 128: s0/qv/denom.
// ---------------------------------------------------------------------------
__global__ void kp_prep(const float* __restrict__ w1, const float* __restrict__ w2,
                        const float* __restrict__ ne,
                        const float* __restrict__ wkq_w,
                        const float* __restrict__ wkq_b,
                        const float* __restrict__ wgactq_w,
                        const float* __restrict__ wgactq_b) {
    int t = threadIdx.x;
    if (blockIdx.x < 128) {
        int g = blockIdx.x * 256 + t;            // 0..32767
        int mat = g >> 14;
        int r = g & 16383;
        int n = r & 255;
        int k0 = (r >> 8) * 4;
        const float* W = mat ? w2 : w1;
        __half* T = mat ? d_B2 : d_B1;
        float x0 = W[(k0+0)*256 + n], x1 = W[(k0+1)*256 + n];
        float x2 = W[(k0+2)*256 + n], x3 = W[(k0+3)*256 + n];
        *(uint2*)(T + n*256 + k0) = make_uint2(pack16(x0, x1), pack16(x2, x3));
        return;
    }
    // block 128: tiny prep
    __shared__ float sq[128];
    __shared__ float sk[16][8];
    d_denom[t] = 0.f;
    if (t < 128) {
        float acc = wkq_b[128 + t];
        #pragma unroll 8
        for (int m = 0; m < 128; m++) acc += ne[m] * wkq_w[m*256 + 128 + t];
        sq[t] = acc;
    } else {
        int idx = t - 128, n = idx >> 3, h = idx & 7, col = h * 16;
        const float* nerow = ne + n*128;
        float acc = wkq_b[col];
        #pragma unroll 8
        for (int m = 0; m < 128; m++) acc += nerow[m] * wkq_w[m*256 + col];
        sk[n][h] = acc;
    }
    __syncthreads();
    if (t < 8) {
        float l[16], mx = -1e30f;
        #pragma unroll
        for (int j = 0; j < 16; j++) { l[j] = sq[t*16 + j] + sk[j][t]; mx = fmaxf(mx, l[j]); }
        float s = 0.f;
        #pragma unroll
        for (int j = 0; j < 16; j++) { l[j] = expf(l[j] - mx); s += l[j]; }
        #pragma unroll
        for (int j = 0; j < 16; j++) d_s0[t*16 + j] = l[j] / s;
    } else if (t < 16) {
        int nh = t - 8;
        const float* nerow = ne + 14*128;
        float acc = wgactq_b[nh];
        #pragma unroll 8
        for (int m = 0; m < 128; m++) acc += nerow[m] * wgactq_w[m*8 + nh];
        d_qv[nh] = acc;
    }
}

// ---------------------------------------------------------------------------
// K1: g = relu(qv + inps @ wgactk + b) + per-(b,h) denom  (lean)
// ---------------------------------------------------------------------------
__global__ void k1_act(const float* __restrict__ inps,
                       const float* __restrict__ wk,
                       const float* __restrict__ wkb) {
    __shared__ float sw[8 * 256];
    __shared__ float sden[NHEAD];
    int t = threadIdx.x;
    for (int i = t; i < 2048; i += 256) {
        int c = i >> 3, nh = i & 7;
        sw[nh*256 + c] = wk[i];
    }
    if (t < 8) sden[t] = 0.f;
    __syncthreads();
    int b = blockIdx.y;
    int lane = t & 31, warp = t >> 5;
    int pix0 = b * 4096 + blockIdx.x * 256;
    for (int it = warp; it < 256; it += 8) {
        int p = pix0 + it;
        const float* row = inps + (size_t)p * 256;
        float acc[8];
        #pragma unroll
        for (int n = 0; n < 8; n++) acc[n] = 0.f;
        #pragma unroll
        for (int q = 0; q < 8; q++) {
            float xv = row[lane + 32*q];
            #pragma unroll
            for (int n = 0; n < 8; n++) acc[n] += xv * sw[n*256 + lane + 32*q];
        }
        #pragma unroll
        for (int off = 16; off; off >>= 1)
            #pragma unroll
            for (int n = 0; n < 8; n++) acc[n] += __shfl_xor_sync(0xffffffffu, acc[n], off);
        if (lane < 8) {
            float gv = fmaxf(0.f, d_qv[lane] + acc[lane] + wkb[lane]);
            d_g[(size_t)p*8 + lane] = gv;
            atomicAdd(&sden[lane], gv);
        }
    }
    __syncthreads();
    if (t < 8) atomicAdd(&d_denom[b*8 + t], sden[t]);
}

// ---------------------------------------------------------------------------
// mma.sync fp16 GEMM. Block 128x256, 16 warps (32x64), K-step 32,
// double-buffered smem.
// MODE 0: A = fp32 inps staged via cp.async, split-2 fp16 in-loop; v out fp16.
// MODE 1: A = single fp16 (d_acc) via cp.async; 1-product; fp32 out.
// ---------------------------------------------------------------------------
#define SA_H 0
#define SA_L 10240
#define SB_  20480
#define BUFSTR 40960
#define SSTG  (2*BUFSTR)             /* fp32 staging: 2 x 16384 */
#define SBIAS (SSTG + 32768)
#define SMT   (SBIAS + 1024)

template<int MODE>
__global__ void __launch_bounds__(512) gemm_mma(const float* __restrict__ Afp,
                                                const float* __restrict__ bias,
                                                float* __restrict__ outp) {
    extern __shared__ char smc[];
    const __half* Bg = (MODE == 0) ? d_B1 : d_B2;

    int t = threadIdx.x, lane = t & 31, wid = t >> 5;
    int wm = wid & 3, wn = wid >> 2;         // 4 x 4 warp grid, 32x64 tiles
    int bm = blockIdx.x * 128;
    uint32_t sb = smem_u32(smc);

    float* sbias = (float*)(smc + SBIAS);
    if (t < 256) sbias[t] = bias[t];

    auto issue = [&](int kc, int buf) {
        uint32_t base = sb + buf * BUFSTR;
        if (MODE == 0) {
            uint32_t stg = sb + SSTG + buf * 16384;
            #pragma unroll
            for (int j = 0; j < 2; j++) {
                int idx = t + 512*j;
                int row = idx >> 3, seg = idx & 7;
                cpa16(stg + (uint32_t)idx * 16,
                      Afp + (size_t)(bm + row) * 256 + kc * 32 + seg * 4);
            }
        } else {
            int arow = t >> 2, aseg = t & 3;
            uint32_t dstA = (uint32_t)(arow * 80 + aseg * 16);
            cpa16(base + SA_H + dstA, d_acc + (size_t)(bm + arow) * 256 + kc * 32 + aseg * 8);
        }
        #pragma unroll
        for (int j = 0; j < 2; j++) {
            int idx = t + 512 * j;
            int brow = idx >> 2, bseg = idx & 3;
            uint32_t dstB = (uint32_t)(brow * 80 + bseg * 16);
            cpa16(base + SB_ + dstB, Bg + (size_t)brow * 256 + kc * 32 + bseg * 8);
        }
        CP_COMMIT();
    };

    auto convertA = [&](int kc) {
        if (MODE != 0) return;
        int buf = kc & 1;
        const char* stg = smc + SSTG + buf * 16384;
        #pragma unroll
        for (int j = 0; j < 2; j++) {
            int idx = t + 512*j;
            int row = idx >> 3, c4 = idx & 7;
            float4 x = *(const float4*)(stg + (size_t)idx * 16);
            float ra, rb, rc, rd;
            uint32_t h01 = pack_hi16(x.x, x.y, ra, rb);
            uint32_t h23 = pack_hi16(x.z, x.w, rc, rd);
            uint32_t off = (uint32_t)(buf * BUFSTR + row * 80 + c4 * 8);
            *(uint2*)(smc + SA_H + off) = make_uint2(h01, h23);
            *(uint2*)(smc + SA_L + off) = make_uint2(pack16(ra, rb), pack16(rc, rd));
        }
    };

    int mat = lane >> 3, r8 = lane & 7;
    uint32_t aBase = (uint32_t)((wm*32 + (mat & 1)*8 + r8) * 80 + ((mat >> 1)*8) * 2);
    uint32_t bBase = (uint32_t)((wn*64 + (mat >> 1)*8 + r8) * 80 + ((mat & 1)*8) * 2);

    float acc[2][8][4];
    #pragma unroll
    for (int i = 0; i < 2; i++)
        #pragma unroll
        for (int j = 0; j < 8; j++)
            #pragma unroll
            for (int q = 0; q < 4; q++) acc[i][j][q] = 0.f;

    issue(0, 0);
    issue(1, 1);
    CP_WAIT1();                 // group 0 arrived
    __syncthreads();
    convertA(0);
    __syncthreads();

    #pragma unroll
    for (int ks = 0; ks < 8; ks++) {
        int buf = ks & 1;
        uint32_t abuf = sb + buf * BUFSTR;

        #pragma unroll
        for (int kk = 0; kk < 2; kk++) {
            uint32_t kb = kk * 32;
            uint32_t ah[2][4], al[2][4];
            #pragma unroll
            for (int mt = 0; mt < 2; mt++) {
                ldm_x4(ah[mt], abuf + SA_H + aBase + mt*16*80 + kb);
                if (MODE == 0) ldm_x4(al[mt], abuf + SA_L + aBase + mt*16*80 + kb);
            }
            #pragma unroll
            for (int h = 0; h < 2; h++) {
                uint32_t bh[4][2];
                #pragma unroll
                for (int pp = 0; pp < 2; pp++) {
                    int p = 2*h + pp;
                    uint32_t tmp[4];
                    ldm_x4(tmp, abuf + SB_ + bBase + p*16*80 + kb);
                    bh[2*pp][0] = tmp[0]; bh[2*pp][1] = tmp[1];
                    bh[2*pp+1][0] = tmp[2]; bh[2*pp+1][1] = tmp[3];
                }
                #pragma unroll
                for (int mt = 0; mt < 2; mt++)
                    #pragma unroll
                    for (int nn = 0; nn < 4; nn++) {
                        int nt = 4*h + nn;
                        mma_f16(acc[mt][nt], ah[mt], bh[nn]);
                        if (MODE == 0) mma_f16(acc[mt][nt], al[mt], bh[nn]);
                    }
            }
        }
        __syncthreads();                       // MMA reads done before refill

        if (ks < 6) issue(ks + 2, buf);        // refill buffer just freed
        if (ks < 7) {
            if (ks < 6) { CP_WAIT1(); } else { CP_WAIT0(); }   // group ks+1 arrived
            __syncthreads();
            convertA(ks + 1);
            __syncthreads();
        }
    }

    // epilogue
    int bb = bm >> 12;
    float invd0 = 0.f, invd1 = 0.f;
    if (MODE == 0) {
        invd0 = 4096.f / (d_denom[bb*8 + wn*2 + 0] + 1e-6f);
        invd1 = 4096.f / (d_denom[bb*8 + wn*2 + 1] + 1e-6f);
    }
    #pragma unroll
    for (int mt = 0; mt < 2; mt++) {
        #pragma unroll
        for (int hf = 0; hf < 2; hf++) {
            int row = bm + wm*32 + mt*16 + hf*8 + (lane >> 2);
            float g0 = 0.f, g1 = 0.f;
            if (MODE == 0) {
                g0 = d_g[(size_t)row*8 + wn*2 + 0] * invd0;
                g1 = d_g[(size_t)row*8 + wn*2 + 1] * invd1;
            }
            #pragma unroll
            for (int nt = 0; nt < 8; nt++) {
                int col = wn*64 + nt*8 + (lane & 3)*2;
                float v0 = acc[mt][nt][hf*2+0] + sbias[col];
                float v1 = acc[mt][nt][hf*2+1] + sbias[col + 1];
                if (MODE == 0) {
                    float s = (nt < 4) ? g0 : g1;
                    v0 *= s; v1 *= s;
                    *(uint32_t*)(d_v + (size_t)row * 256 + col) = pack16(v0, v1);
                } else {
                    *(float2*)(outp + (size_t)row * 256 + col) = make_float2(v0, v1);
                }
            }
        }
    }
}

// ---------------------------------------------------------------------------
// K4a: patch gather, fp16 v input (uint2 = 4 ch), 2x2 output tile per block,
// fp32 accumulate, single fp16 output.
// ---------------------------------------------------------------------------
__global__ void __launch_bounds__(256) k4a_gather() {
    __shared__ float ss0[128];
    int t = threadIdx.x;
    if (t < 128) ss0[t] = d_s0[t];
    __syncthreads();

    int op = blockIdx.x;                    // 0..8191
    int b  = op >> 8;
    int xt = (op >> 4) & 15, yt = op & 15;
    int out = t >> 6;
    int x = 2*xt + (out >> 1);
    int y = 2*yt + (out & 1);
    int cq = t & 63;                        // 4-channel group index
    int h = cq >> 3;

    float s[16];
    #pragma unroll
    for (int n = 0; n < 16; n++) s[n] = ss0[h*16 + n];

    float4 a4 = make_float4(0.f, 0.f, 0.f, 0.f);
    #pragma unroll
    for (int i = 0; i < 4; i++) {
        int sh = 2*x + i - 1;
        if ((unsigned)sh >= 64u) continue;
        #pragma unroll
        for (int j = 0; j < 4; j++) {
            int sw = 2*y + j - 1;
            if ((unsigned)sw >= 64u) continue;
            uint2 raw = *(const uint2*)(d_v + ((((size_t)b*64 + sh)*64 + sw)*256) + cq*4);
            float2 v01 = __half22float2(*(__half2*)&raw.x);
            float2 v23 = __half22float2(*(__half2*)&raw.y);
            float w = s[i*4 + j];
            a4.x += w * v01.x; a4.y += w * v01.y;
            a4.z += w * v23.x; a4.w += w * v23.y;
        }
    }

    size_t idx = ((size_t)((b*32 + x)*32 + y))*256 + cq*4;
    *(uint2*)(d_acc + idx) = make_uint2(pack16(a4.x, a4.y), pack16(a4.z, a4.w));
}

// ---------------------------------------------------------------------------
extern "C" void kernel_launch(void* const* d_in, const int* in_sizes, int n_in,
                              void* d_out, int out_size) {
    const float* inps     = (const float*)d_in[0];
    const float* ne       = (const float*)d_in[1];
    const float* wkq_w    = (const float*)d_in[2];
    const float* wkq_b    = (const float*)d_in[3];
    const float* wv_w     = (const float*)d_in[4];
    const float* wv_b     = (const float*)d_in[5];
    const float* wgactq_w = (const float*)d_in[6];
    const float* wgactq_b = (const float*)d_in[7];
    const float* wgactk_w = (const float*)d_in[8];
    const float* wgactk_b = (const float*)d_in[9];
    const float* wf_w     = (const float*)d_in[10];
    const float* wf_b     = (const float*)d_in[11];
    float* out = (float*)d_out;

    static int inited = 0;
    if (!inited) {
        cudaFuncSetAttribute(gemm_mma<0>, cudaFuncAttributeMaxDynamicSharedMemorySize, SMT);
        cudaFuncSetAttribute(gemm_mma<1>, cudaFuncAttributeMaxDynamicSharedMemorySize, SMT);
        inited = 1;
    }

    kp_prep<<<129, 256>>>(wv_w, wf_w, ne, wkq_w, wkq_b, wgactq_w, wgactq_b);
    k1_act<<<dim3(16, 32), 256>>>(inps, wgactk_w, wgactk_b);
    gemm_mma<0><<<1024, 512, SMT>>>(inps, wv_b, nullptr);
    k4a_gather<<<8192, 256>>>();
    gemm_mma<1><<<256, 512, SMT>>>(nullptr, wf_b, out);
}

// round 15
// speedup vs baseline: 1.4738x; 1.0904x over previous
#include <cuda_runtime.h>
#include <cuda_fp16.h>
#include <cstdint>

#define B_    32
#define NHEAD 8
#define NPIX  (B_*64*64)       /* 131072 */
#define NOUT  (B_*32*32)       /* 32768  */

__device__ float d_s0[NHEAD*16];
__device__ float d_qv[NHEAD];
__device__ float d_g[(size_t)NPIX*NHEAD];
__device__ float d_denom[B_*NHEAD];
__device__ __half d_v[(size_t)NPIX*256];          /* v in fp16 */
__device__ __half d_acc[(size_t)NOUT*256];        /* gathered acc, fp16 */
__device__ __half d_B1[65536], d_B2[65536];       /* W^T [n][k], fp16 */

// ---------------------------------------------------------------- helpers
__device__ __forceinline__ uint32_t smem_u32(const void* p) {
    uint32_t a;
    asm("{ .reg .u64 t; cvta.to.shared.u64 t, %1; cvt.u32.u64 %0, t; }" : "=r"(a) : "l"(p));
    return a;
}
__device__ __forceinline__ void ldm_x4(uint32_t* r, uint32_t addr) {
    asm volatile("ldmatrix.sync.aligned.m8n8.x4.shared.b16 {%0,%1,%2,%3}, [%4];"
        : "=r"(r[0]), "=r"(r[1]), "=r"(r[2]), "=r"(r[3]) : "r"(addr));
}
__device__ __forceinline__ void mma_f16(float* c, const uint32_t* a, const uint32_t* b) {
    asm volatile("mma.sync.aligned.m16n8k16.row.col.f32.f16.f16.f32 "
        "{%0,%1,%2,%3}, {%4,%5,%6,%7}, {%8,%9}, {%0,%1,%2,%3};"
        : "+f"(c[0]), "+f"(c[1]), "+f"(c[2]), "+f"(c[3])
        : "r"(a[0]), "r"(a[1]), "r"(a[2]), "r"(a[3]), "r"(b[0]), "r"(b[1]));
}
__device__ __forceinline__ void cpa16(uint32_t dst, const void* src) {
    asm volatile("cp.async.ca.shared.global [%0], [%1], 16;" :: "r"(dst), "l"(src) : "memory");
}
#define CP_COMMIT() asm volatile("cp.async.commit_group;" ::: "memory")
#define CP_WAIT0()  asm volatile("cp.async.wait_group 0;" ::: "memory")
#define CP_WAIT1()  asm volatile("cp.async.wait_group 1;" ::: "memory")

__device__ __forceinline__ uint32_t pack16(float a, float b) {
    return (uint32_t)__half_as_ushort(__float2half_rn(a)) |
           ((uint32_t)__half_as_ushort(__float2half_rn(b)) << 16);
}

// ---------------------------------------------------------------------------
// KP: merged prep. Blocks 0..127: weight transpose to fp16. Block 128: s0/qv/denom.
// ---------------------------------------------------------------------------
__global__ void kp_prep(const float* __restrict__ w1, const float* __restrict__ w2,
                        const float* __restrict__ ne,
                        const float* __restrict__ wkq_w,
                        const float* __restrict__ wkq_b,
                        const float* __restrict__ wgactq_w,
                        const float* __restrict__ wgactq_b) {
    int t = threadIdx.x;
    if (blockIdx.x < 128) {
        int g = blockIdx.x * 256 + t;            // 0..32767
        int mat = g >> 14;
        int r = g & 16383;
        int n = r & 255;
        int k0 = (r >> 8) * 4;
        const float* W = mat ? w2 : w1;
        __half* T = mat ? d_B2 : d_B1;
        float x0 = W[(k0+0)*256 + n], x1 = W[(k0+1)*256 + n];
        float x2 = W[(k0+2)*256 + n], x3 = W[(k0+3)*256 + n];
        *(uint2*)(T + n*256 + k0) = make_uint2(pack16(x0, x1), pack16(x2, x3));
        return;
    }
    // block 128: tiny prep
    __shared__ float sq[128];
    __shared__ float sk[16][8];
    d_denom[t] = 0.f;
    if (t < 128) {
        float acc = wkq_b[128 + t];
        #pragma unroll 8
        for (int m = 0; m < 128; m++) acc += ne[m] * wkq_w[m*256 + 128 + t];
        sq[t] = acc;
    } else {
        int idx = t - 128, n = idx >> 3, h = idx & 7, col = h * 16;
        const float* nerow = ne + n*128;
        float acc = wkq_b[col];
        #pragma unroll 8
        for (int m = 0; m < 128; m++) acc += nerow[m] * wkq_w[m*256 + col];
        sk[n][h] = acc;
    }
    __syncthreads();
    if (t < 8) {
        float l[16], mx = -1e30f;
        #pragma unroll
        for (int j = 0; j < 16; j++) { l[j] = sq[t*16 + j] + sk[j][t]; mx = fmaxf(mx, l[j]); }
        float s = 0.f;
        #pragma unroll
        for (int j = 0; j < 16; j++) { l[j] = expf(l[j] - mx); s += l[j]; }
        #pragma unroll
        for (int j = 0; j < 16; j++) d_s0[t*16 + j] = l[j] / s;
    } else if (t < 16) {
        int nh = t - 8;
        const float* nerow = ne + 14*128;
        float acc = wgactq_b[nh];
        #pragma unroll 8
        for (int m = 0; m < 128; m++) acc += nerow[m] * wgactq_w[m*8 + nh];
        d_qv[nh] = acc;
    }
}

// ---------------------------------------------------------------------------
// K1: g = relu(qv + inps @ wgactk + b) + per-(b,h) denom  (lean)
// ---------------------------------------------------------------------------
__global__ void k1_act(const float* __restrict__ inps,
                       const float* __restrict__ wk,
                       const float* __restrict__ wkb) {
    __shared__ float sw[8 * 256];
    __shared__ float sden[NHEAD];
    int t = threadIdx.x;
    for (int i = t; i < 2048; i += 256) {
        int c = i >> 3, nh = i & 7;
        sw[nh*256 + c] = wk[i];
    }
    if (t < 8) sden[t] = 0.f;
    __syncthreads();
    int b = blockIdx.y;
    int lane = t & 31, warp = t >> 5;
    int pix0 = b * 4096 + blockIdx.x * 256;
    for (int it = warp; it < 256; it += 8) {
        int p = pix0 + it;
        const float* row = inps + (size_t)p * 256;
        float acc[8];
        #pragma unroll
        for (int n = 0; n < 8; n++) acc[n] = 0.f;
        #pragma unroll
        for (int q = 0; q < 8; q++) {
            float xv = row[lane + 32*q];
            #pragma unroll
            for (int n = 0; n < 8; n++) acc[n] += xv * sw[n*256 + lane + 32*q];
        }
        #pragma unroll
        for (int off = 16; off; off >>= 1)
            #pragma unroll
            for (int n = 0; n < 8; n++) acc[n] += __shfl_xor_sync(0xffffffffu, acc[n], off);
        if (lane < 8) {
            float gv = fmaxf(0.f, d_qv[lane] + acc[lane] + wkb[lane]);
            d_g[(size_t)p*8 + lane] = gv;
            atomicAdd(&sden[lane], gv);
        }
    }
    __syncthreads();
    if (t < 8) atomicAdd(&d_denom[b*8 + t], sden[t]);
}

// ---------------------------------------------------------------------------
// mma.sync fp16 single-product GEMM. Block 128x256, 16 warps (32x64),
// K-step 32, double-buffered smem.
// MODE 0: A = fp32 inps staged via cp.async, fp16-converted in-loop; v out fp16.
// MODE 1: A = fp16 (d_acc) via cp.async; fp32 out.
// ---------------------------------------------------------------------------
#define SA_   0
#define SB_   10240
#define BUFSTR 30720
#define SSTG  (2*BUFSTR)             /* fp32 staging: 2 x 16384 */
#define SBIAS (SSTG + 32768)
#define SMT   (SBIAS + 1024)

template<int MODE>
__global__ void __launch_bounds__(512) gemm_mma(const float* __restrict__ Afp,
                                                const float* __restrict__ bias,
                                                float* __restrict__ outp) {
    extern __shared__ char smc[];
    const __half* Bg = (MODE == 0) ? d_B1 : d_B2;

    int t = threadIdx.x, lane = t & 31, wid = t >> 5;
    int wm = wid & 3, wn = wid >> 2;         // 4 x 4 warp grid, 32x64 tiles
    int bm = blockIdx.x * 128;
    uint32_t sb = smem_u32(smc);

    float* sbias = (float*)(smc + SBIAS);
    if (t < 256) sbias[t] = bias[t];

    auto issue = [&](int kc, int buf) {
        uint32_t base = sb + buf * BUFSTR;
        if (MODE == 0) {
            uint32_t stg = sb + SSTG + buf * 16384;
            #pragma unroll
            for (int j = 0; j < 2; j++) {
                int idx = t + 512*j;
                int row = idx >> 3, seg = idx & 7;
                cpa16(stg + (uint32_t)idx * 16,
                      Afp + (size_t)(bm + row) * 256 + kc * 32 + seg * 4);
            }
        } else {
            int arow = t >> 2, aseg = t & 3;
            uint32_t dstA = (uint32_t)(arow * 80 + aseg * 16);
            cpa16(base + SA_ + dstA, d_acc + (size_t)(bm + arow) * 256 + kc * 32 + aseg * 8);
        }
        #pragma unroll
        for (int j = 0; j < 2; j++) {
            int idx = t + 512 * j;
            int brow = idx >> 2, bseg = idx & 3;
            uint32_t dstB = (uint32_t)(brow * 80 + bseg * 16);
            cpa16(base + SB_ + dstB, Bg + (size_t)brow * 256 + kc * 32 + bseg * 8);
        }
        CP_COMMIT();
    };

    auto convertA = [&](int kc) {
        if (MODE != 0) return;
        int buf = kc & 1;
        const char* stg = smc + SSTG + buf * 16384;
        #pragma unroll
        for (int j = 0; j < 2; j++) {
            int idx = t + 512*j;
            int row = idx >> 3, c4 = idx & 7;
            float4 x = *(const float4*)(stg + (size_t)idx * 16);
            uint32_t off = (uint32_t)(buf * BUFSTR + row * 80 + c4 * 8);
            *(uint2*)(smc + SA_ + off) = make_uint2(pack16(x.x, x.y), pack16(x.z, x.w));
        }
    };

    int mat = lane >> 3, r8 = lane & 7;
    uint32_t aBase = (uint32_t)((wm*32 + (mat & 1)*8 + r8) * 80 + ((mat >> 1)*8) * 2);
    uint32_t bBase = (uint32_t)((wn*64 + (mat >> 1)*8 + r8) * 80 + ((mat & 1)*8) * 2);

    float acc[2][8][4];
    #pragma unroll
    for (int i = 0; i < 2; i++)
        #pragma unroll
        for (int j = 0; j < 8; j++)
            #pragma unroll
            for (int q = 0; q < 4; q++) acc[i][j][q] = 0.f;

    issue(0, 0);
    issue(1, 1);
    CP_WAIT1();                 // group 0 arrived
    __syncthreads();
    convertA(0);
    __syncthreads();

    #pragma unroll
    for (int ks = 0; ks < 8; ks++) {
        int buf = ks & 1;
        uint32_t abuf = sb + buf * BUFSTR;

        #pragma unroll
        for (int kk = 0; kk < 2; kk++) {
            uint32_t kb = kk * 32;
            uint32_t ah[2][4];
            #pragma unroll
            for (int mt = 0; mt < 2; mt++)
                ldm_x4(ah[mt], abuf + SA_ + aBase + mt*16*80 + kb);
            #pragma unroll
            for (int h = 0; h < 2; h++) {
                uint32_t bh[4][2];
                #pragma unroll
                for (int pp = 0; pp < 2; pp++) {
                    int p = 2*h + pp;
                    uint32_t tmp[4];
                    ldm_x4(tmp, abuf + SB_ + bBase + p*16*80 + kb);
                    bh[2*pp][0] = tmp[0]; bh[2*pp][1] = tmp[1];
                    bh[2*pp+1][0] = tmp[2]; bh[2*pp+1][1] = tmp[3];
                }
                #pragma unroll
                for (int mt = 0; mt < 2; mt++)
                    #pragma unroll
                    for (int nn = 0; nn < 4; nn++)
                        mma_f16(acc[mt][4*h + nn], ah[mt], bh[nn]);
            }
        }
        __syncthreads();                       // MMA reads done before refill

        if (ks < 6) issue(ks + 2, buf);        // refill buffer just freed
        if (ks < 7) {
            if (ks < 6) { CP_WAIT1(); } else { CP_WAIT0(); }   // group ks+1 arrived
            __syncthreads();
            convertA(ks + 1);
            __syncthreads();
        }
    }

    // epilogue
    int bb = bm >> 12;
    float invd0 = 0.f, invd1 = 0.f;
    if (MODE == 0) {
        invd0 = 4096.f / (d_denom[bb*8 + wn*2 + 0] + 1e-6f);
        invd1 = 4096.f / (d_denom[bb*8 + wn*2 + 1] + 1e-6f);
    }
    #pragma unroll
    for (int mt = 0; mt < 2; mt++) {
        #pragma unroll
        for (int hf = 0; hf < 2; hf++) {
            int row = bm + wm*32 + mt*16 + hf*8 + (lane >> 2);
            float g0 = 0.f, g1 = 0.f;
            if (MODE == 0) {
                g0 = d_g[(size_t)row*8 + wn*2 + 0] * invd0;
                g1 = d_g[(size_t)row*8 + wn*2 + 1] * invd1;
            }
            #pragma unroll
            for (int nt = 0; nt < 8; nt++) {
                int col = wn*64 + nt*8 + (lane & 3)*2;
                float v0 = acc[mt][nt][hf*2+0] + sbias[col];
                float v1 = acc[mt][nt][hf*2+1] + sbias[col + 1];
                if (MODE == 0) {
                    float s = (nt < 4) ? g0 : g1;
                    v0 *= s; v1 *= s;
                    *(uint32_t*)(d_v + (size_t)row * 256 + col) = pack16(v0, v1);
                } else {
                    *(float2*)(outp + (size_t)row * 256 + col) = make_float2(v0, v1);
                }
            }
        }
    }
}

// ---------------------------------------------------------------------------
// K4a: patch gather, uint4 loads (8 ch/thread), 2x4 output tile per block,
// fp32 accumulate, fp16 output.
// ---------------------------------------------------------------------------
__global__ void __launch_bounds__(256) k4a_gather() {
    __shared__ float ss0[128];
    int t = threadIdx.x;
    if (t < 128) ss0[t] = d_s0[t];
    __syncthreads();

    int op = blockIdx.x;                    // 0..4095
    int b  = op >> 7;                       // 32 batches, 128 blocks each
    int xt = (op >> 3) & 15, yt = op & 7;   // 16 x 8 tiles of 2x4 outputs
    int out = t >> 5;                       // 0..7
    int x = 2*xt + (out >> 2);
    int y = 4*yt + (out & 3);
    int c8 = t & 31;                        // 8-channel group index
    int h = c8 >> 2;

    float s[16];
    #pragma unroll
    for (int n = 0; n < 16; n++) s[n] = ss0[h*16 + n];

    float a8[8];
    #pragma unroll
    for (int q = 0; q < 8; q++) a8[q] = 0.f;

    #pragma unroll
    for (int i = 0; i < 4; i++) {
        int sh = 2*x + i - 1;
        if ((unsigned)sh >= 64u) continue;
        #pragma unroll
        for (int j = 0; j < 4; j++) {
            int sw = 2*y + j - 1;
            if ((unsigned)sw >= 64u) continue;
            uint4 raw = *(const uint4*)(d_v + ((((size_t)b*64 + sh)*64 + sw)*256) + c8*8);
            float w = s[i*4 + j];
            float2 p0 = __half22float2(*(__half2*)&raw.x);
            float2 p1 = __half22float2(*(__half2*)&raw.y);
            float2 p2 = __half22float2(*(__half2*)&raw.z);
            float2 p3 = __half22float2(*(__half2*)&raw.w);
            a8[0] += w * p0.x; a8[1] += w * p0.y;
            a8[2] += w * p1.x; a8[3] += w * p1.y;
            a8[4] += w * p2.x; a8[5] += w * p2.y;
            a8[6] += w * p3.x; a8[7] += w * p3.y;
        }
    }

    size_t idx = ((size_t)((b*32 + x)*32 + y))*256 + c8*8;
    uint4 o;
    o.x = pack16(a8[0], a8[1]);
    o.y = pack16(a8[2], a8[3]);
    o.z = pack16(a8[4], a8[5]);
    o.w = pack16(a8[6], a8[7]);
    *(uint4*)(d_acc + idx) = o;
}

// ---------------------------------------------------------------------------
extern "C" void kernel_launch(void* const* d_in, const int* in_sizes, int n_in,
                              void* d_out, int out_size) {
    const float* inps     = (const float*)d_in[0];
    const float* ne       = (const float*)d_in[1];
    const float* wkq_w    = (const float*)d_in[2];
    const float* wkq_b    = (const float*)d_in[3];
    const float* wv_w     = (const float*)d_in[4];
    const float* wv_b     = (const float*)d_in[5];
    const float* wgactq_w = (const float*)d_in[6];
    const float* wgactq_b = (const float*)d_in[7];
    const float* wgactk_w = (const float*)d_in[8];
    const float* wgactk_b = (const float*)d_in[9];
    const float* wf_w     = (const float*)d_in[10];
    const float* wf_b     = (const float*)d_in[11];
    float* out = (float*)d_out;

    static int inited = 0;
    if (!inited) {
        cudaFuncSetAttribute(gemm_mma<0>, cudaFuncAttributeMaxDynamicSharedMemorySize, SMT);
        cudaFuncSetAttribute(gemm_mma<1>, cudaFuncAttributeMaxDynamicSharedMemorySize, SMT);
        inited = 1;
    }

    kp_prep<<<129, 256>>>(wv_w, wf_w, ne, wkq_w, wkq_b, wgactq_w, wgactq_b);
    k1_act<<<dim3(16, 32), 256>>>(inps, wgactk_w, wgactk_b);
    gemm_mma<0><<<1024, 512, SMT>>>(inps, wv_b, nullptr);
    k4a_gather<<<4096, 256>>>();
    gemm_mma<1><<<256, 512, SMT>>>(nullptr, wf_b, out);
}